// round 1
// baseline (speedup 1.0000x reference)
#include <cuda_runtime.h>
#include <math.h>

#define NN   20000
#define EE   320000
#define FIN  518
#define DD   128
#define EDIM 32
#define HH   4
#define HID  256
#define ETOT (EE + NN)

// ---------------- scratch (static device globals; no allocation) ----------------
__device__ float g_h1[(size_t)NN * HID];          // node encoder hidden
__device__ float g_x[(size_t)NN * DD];            // current layer input
__device__ float g_ea[(size_t)EE * EDIM];         // edge attrs
__device__ float g_loop[(size_t)NN * EDIM];       // self-loop attrs (mean)
__device__ float g_cnt[NN];
__device__ float g_hH[(size_t)NN * HH * DD];      // per-head transformed feats
__device__ float g_as[NN * HH];
__device__ float g_ad[NN * HH];
__device__ float g_alpha[(size_t)ETOT * HH];      // raw -> exp
__device__ float g_amax[NN * HH];
__device__ float g_den[NN * HH];
__device__ float g_agg[(size_t)NN * HH * DD];
__device__ float g_we[HH * EDIM];                 // folded lin_e * att_e

// ---------------- helpers ----------------
__device__ __forceinline__ void atomicMaxFloat(float* addr, float val) {
    if (val >= 0.0f)
        atomicMax((int*)addr, __float_as_int(val));
    else
        atomicMin((unsigned int*)addr, __float_as_uint(val));
}

__device__ __forceinline__ void redAdd4(float* p, float4 v) {
    asm volatile("red.global.add.v4.f32 [%0], {%1,%2,%3,%4};"
                 :: "l"(p), "f"(v.x), "f"(v.y), "f"(v.z), "f"(v.w) : "memory");
}

// ---------------- kernels ----------------
__global__ void zero_once() {
    int i = blockIdx.x * blockDim.x + threadIdx.x;
    if (i < NN) g_cnt[i] = 0.0f;
    if (i < NN * EDIM) g_loop[i] = 0.0f;
}

__global__ void gather_ea(const int* __restrict__ et, const int* __restrict__ dst,
                          const float* __restrict__ rel) {
    int eg = (blockIdx.x * blockDim.x + threadIdx.x) >> 5;
    int l = threadIdx.x & 31;
    if (eg >= EE) return;
    int t = et[eg];
    int d = dst[eg];
    float v = rel[t * EDIM + l];
    g_ea[(size_t)eg * EDIM + l] = v;
    atomicAdd(&g_loop[d * EDIM + l], v);
    if (l == 0) atomicAdd(&g_cnt[d], 1.0f);
}

__global__ void loop_div() {
    int i = blockIdx.x * blockDim.x + threadIdx.x;
    if (i >= NN * EDIM) return;
    int n = i / EDIM;
    g_loop[i] /= fmaxf(g_cnt[n], 1.0f);
}

// tiled SGEMM: C[M,Nn] = A[M,K] @ B[K,Nn] (+bias) (+relu)
__global__ void sgemm128(const float* __restrict__ A, const float* __restrict__ B,
                         const float* __restrict__ bias, float* __restrict__ C,
                         int M, int K, int Nn, int doRelu) {
    const int BM = 128, BN = 128, BK = 8, TM = 8, TN = 8;
    __shared__ float As[BK][BM];
    __shared__ float Bs[BK][BN];
    int tid = threadIdx.x;                 // 256 threads
    int tcol = tid % (BN / TN);            // 16
    int trow = tid / (BN / TN);            // 16
    int rowBase = blockIdx.y * BM;
    int colBase = blockIdx.x * BN;
    float acc[TM][TN];
#pragma unroll
    for (int i = 0; i < TM; i++)
#pragma unroll
        for (int j = 0; j < TN; j++) acc[i][j] = 0.0f;

    for (int k0 = 0; k0 < K; k0 += BK) {
#pragma unroll
        for (int i = tid; i < BM * BK; i += 256) {
            int r = i / BK, c = i % BK;
            int gr = rowBase + r, gc = k0 + c;
            As[c][r] = (gr < M && gc < K) ? A[(size_t)gr * K + gc] : 0.0f;
        }
#pragma unroll
        for (int i = tid; i < BK * BN; i += 256) {
            int r = i / BN, c = i % BN;
            int gr = k0 + r, gc = colBase + c;
            Bs[r][c] = (gr < K && gc < Nn) ? B[(size_t)gr * Nn + gc] : 0.0f;
        }
        __syncthreads();
#pragma unroll
        for (int kk = 0; kk < BK; kk++) {
            float a[TM], b[TN];
#pragma unroll
            for (int i = 0; i < TM; i++) a[i] = As[kk][trow * TM + i];
#pragma unroll
            for (int j = 0; j < TN; j++) b[j] = Bs[kk][tcol * TN + j];
#pragma unroll
            for (int i = 0; i < TM; i++)
#pragma unroll
                for (int j = 0; j < TN; j++) acc[i][j] += a[i] * b[j];
        }
        __syncthreads();
    }
#pragma unroll
    for (int i = 0; i < TM; i++) {
        int gr = rowBase + trow * TM + i;
        if (gr >= M) continue;
#pragma unroll
        for (int j = 0; j < TN; j++) {
            int gc = colBase + tcol * TN + j;
            if (gc >= Nn) continue;
            float v = acc[i][j] + (bias ? bias[gc] : 0.0f);
            if (doRelu) v = fmaxf(v, 0.0f);
            C[(size_t)gr * Nn + gc] = v;
        }
    }
}

// fold lin_e [ED, H*D] with att_e [H, D] -> w_e[h*ED + c]
__global__ void compute_we(const float* __restrict__ line, const float* __restrict__ atte) {
    int idx = threadIdx.x;                // 128 = H*ED
    int h = idx / EDIM, c = idx % EDIM;
    float s = 0.0f;
    for (int d = 0; d < DD; d++)
        s += line[(size_t)c * (HH * DD) + h * DD + d] * atte[h * DD + d];
    g_we[idx] = s;
}

// per-node attention scores a_s, a_d
__global__ void att_nd(const float* __restrict__ atts, const float* __restrict__ attd) {
    int n = blockIdx.x;
    int h = threadIdx.x >> 5;
    int l = threadIdx.x & 31;
    const float* row = g_hH + (size_t)n * (HH * DD) + h * DD;
    float s = 0.0f, d2 = 0.0f;
#pragma unroll
    for (int i = l; i < DD; i += 32) {
        float v = row[i];
        s += v * atts[h * DD + i];
        d2 += v * attd[h * DD + i];
    }
#pragma unroll
    for (int o = 16; o; o >>= 1) {
        s += __shfl_xor_sync(0xffffffffu, s, o);
        d2 += __shfl_xor_sync(0xffffffffu, d2, o);
    }
    if (l == 0) {
        g_as[n * HH + h] = s;
        g_ad[n * HH + h] = d2;
    }
}

__global__ void layer_init() {
    size_t i = blockIdx.x * (size_t)blockDim.x + threadIdx.x;
    if (i < (size_t)NN * HH * DD) g_agg[i] = 0.0f;
    if (i < NN * HH) {
        g_amax[i] = -INFINITY;
        g_den[i] = 0.0f;
    }
}

// pass1: raw alpha = leaky_relu(a_s[s]+a_d[d]+a_e), per-(dst,head) running max
__global__ void alpha_pass1(const int* __restrict__ src, const int* __restrict__ dst) {
    int eg = (blockIdx.x * blockDim.x + threadIdx.x) >> 5;
    int l = threadIdx.x & 31;
    if (eg >= ETOT) return;
    int sN, dN;
    const float* row;
    if (eg < EE) {
        sN = src[eg];
        dN = dst[eg];
        row = g_ea + (size_t)eg * EDIM;
    } else {
        sN = dN = eg - EE;
        row = g_loop + (size_t)(eg - EE) * EDIM;
    }
    float v = row[l];
    float keep = 0.0f;
#pragma unroll
    for (int h = 0; h < HH; h++) {
        float p = v * g_we[h * EDIM + l];
#pragma unroll
        for (int o = 16; o; o >>= 1) p += __shfl_xor_sync(0xffffffffu, p, o);
        if (l == h) keep = p;
    }
    if (l < HH) {
        float raw = g_as[sN * HH + l] + g_ad[dN * HH + l] + keep;
        raw = raw > 0.0f ? raw : 0.2f * raw;
        g_alpha[(size_t)eg * HH + l] = raw;
        atomicMaxFloat(&g_amax[dN * HH + l], raw);
    }
}

// pass2: exp and denominator
__global__ void alpha_pass2(const int* __restrict__ dst) {
    int i = blockIdx.x * blockDim.x + threadIdx.x;
    if (i >= ETOT * HH) return;
    int eg = i >> 2, h = i & 3;
    int dN = (eg < EE) ? dst[eg] : (eg - EE);
    float e = expf(g_alpha[i] - g_amax[dN * HH + h]);
    g_alpha[i] = e;
    atomicAdd(&g_den[dN * HH + h], e);
}

// pass3: scatter-accumulate messages (warp per edge, vector reductions)
__global__ void aggregate(const int* __restrict__ src, const int* __restrict__ dst) {
    int eg = (blockIdx.x * blockDim.x + threadIdx.x) >> 5;
    int l = threadIdx.x & 31;
    if (eg >= ETOT) return;
    int sN, dN;
    if (eg < EE) {
        sN = src[eg];
        dN = dst[eg];
    } else {
        sN = dN = eg - EE;
    }
    float sc[HH];
#pragma unroll
    for (int h = 0; h < HH; h++)
        sc[h] = g_alpha[(size_t)eg * HH + h] / (g_den[dN * HH + h] + 1e-16f);
    const float4* hrow = (const float4*)(g_hH + (size_t)sN * (HH * DD));
    float4* arow = (float4*)(g_agg + (size_t)dN * (HH * DD));
#pragma unroll
    for (int k = 0; k < 4; k++) {            // head == k (32 float4 per head)
        int vi = k * 32 + l;
        float4 v = hrow[vi];
        float s = sc[k];
        v.x *= s; v.y *= s; v.z *= s; v.w *= s;
        redAdd4((float*)(arow + vi), v);
    }
}

// mean over heads + bias + relu
__global__ void finalize(const float* __restrict__ bias, float* __restrict__ out) {
    int i = blockIdx.x * blockDim.x + threadIdx.x;
    if (i >= NN * DD) return;
    int n = i >> 7, dd = i & 127;
    const float* a = g_agg + (size_t)n * (HH * DD) + dd;
    float v = 0.25f * (a[0] + a[DD] + a[2 * DD] + a[3 * DD]) + bias[dd];
    out[i] = fmaxf(v, 0.0f);
}

// ---------------- host ----------------
static float* symaddr(const void* s) {
    void* p = nullptr;
    cudaGetSymbolAddress(&p, s);
    return (float*)p;
}

extern "C" void kernel_launch(void* const* d_in, const int* in_sizes, int n_in,
                              void* d_out, int out_size) {
    const float* x   = (const float*)d_in[0];
    const int*   ei  = (const int*)d_in[1];
    const int*   et  = (const int*)d_in[2];
    const float* w1  = (const float*)d_in[3];
    const float* b1  = (const float*)d_in[4];
    const float* w2  = (const float*)d_in[5];
    const float* b2  = (const float*)d_in[6];
    const float* rel = (const float*)d_in[7];
    const float* lin[2]  = {(const float*)d_in[8],  (const float*)d_in[14]};
    const float* line[2] = {(const float*)d_in[9],  (const float*)d_in[15]};
    const float* atts[2] = {(const float*)d_in[10], (const float*)d_in[16]};
    const float* attd[2] = {(const float*)d_in[11], (const float*)d_in[17]};
    const float* atte[2] = {(const float*)d_in[12], (const float*)d_in[18]};
    const float* bias[2] = {(const float*)d_in[13], (const float*)d_in[19]};
    const int* srcp = ei;
    const int* dstp = ei + EE;

    float* ph1 = symaddr(g_h1);
    float* px  = symaddr(g_x);
    float* phH = symaddr(g_hH);

    zero_once<<<(NN * EDIM + 255) / 256, 256>>>();
    gather_ea<<<(EE * 32 + 255) / 256, 256>>>(et, dstp, rel);
    loop_div<<<(NN * EDIM + 255) / 256, 256>>>();

    // node encoder: h = relu(x@w1+b1)@w2 + b2
    sgemm128<<<dim3((HID + 127) / 128, (NN + 127) / 128), 256>>>(x, w1, b1, ph1, NN, FIN, HID, 1);
    sgemm128<<<dim3((DD + 127) / 128, (NN + 127) / 128), 256>>>(ph1, w2, b2, px, NN, HID, DD, 0);

    for (int L = 0; L < 2; L++) {
        compute_we<<<1, HH * EDIM>>>(line[L], atte[L]);
        sgemm128<<<dim3((HH * DD + 127) / 128, (NN + 127) / 128), 256>>>(
            px, lin[L], nullptr, phH, NN, DD, HH * DD, 0);
        att_nd<<<NN, 128>>>(atts[L], attd[L]);
        layer_init<<<((NN * HH * DD) + 255) / 256, 256>>>();
        alpha_pass1<<<((size_t)ETOT * 32 + 255) / 256, 256>>>(srcp, dstp);
        alpha_pass2<<<(ETOT * HH + 255) / 256, 256>>>(dstp);
        aggregate<<<((size_t)ETOT * 32 + 255) / 256, 256>>>(srcp, dstp);
        finalize<<<((NN * DD) + 255) / 256, 256>>>(bias[L], (L == 0) ? px : (float*)d_out);
    }
}

// round 2
// speedup vs baseline: 1.8312x; 1.8312x over previous
#include <cuda_runtime.h>
#include <math.h>

#define NN   20000
#define EE   320000
#define FIN  518
#define KPAD 528
#define DD   128
#define EDIM 32
#define HH   4
#define HID  256
#define ETOT (EE + NN)

// ---------------- scratch ----------------
__device__ float g_xp[(size_t)NN * KPAD];         // padded input
__device__ float g_h1[(size_t)NN * HID];
__device__ float g_x[(size_t)NN * DD];
__device__ float g_ea[(size_t)EE * EDIM];
__device__ float g_loop[(size_t)NN * EDIM];
__device__ float g_cnt[NN];
__device__ float g_hH[(size_t)NN * HH * DD];
__device__ float g_as[NN * HH];
__device__ float g_ad[NN * HH];
__device__ float g_alpha[(size_t)ETOT * HH];
__device__ float g_we[HH * EDIM];
__device__ int   g_deg[NN + 1];
__device__ int   g_off[NN + 1];
__device__ int   g_cur[NN];
__device__ int   g_eid[EE];

// ---------------- setup kernels ----------------
__global__ void zero_once() {
    int i = blockIdx.x * blockDim.x + threadIdx.x;
    if (i < NN) g_cnt[i] = 0.0f;
    if (i <= NN) g_deg[i] = 0;
    if (i < NN * EDIM) g_loop[i] = 0.0f;
}

__global__ void gather_ea(const int* __restrict__ et, const int* __restrict__ dst,
                          const float* __restrict__ rel) {
    int eg = (blockIdx.x * blockDim.x + threadIdx.x) >> 5;
    int l = threadIdx.x & 31;
    if (eg >= EE) return;
    int t = et[eg];
    int d = dst[eg];
    float v = rel[t * EDIM + l];
    g_ea[(size_t)eg * EDIM + l] = v;
    atomicAdd(&g_loop[d * EDIM + l], v);
    if (l == 0) {
        atomicAdd(&g_cnt[d], 1.0f);
        atomicAdd(&g_deg[d], 1);
    }
}

__global__ void loop_div() {
    int i = blockIdx.x * blockDim.x + threadIdx.x;
    if (i >= NN * EDIM) return;
    int n = i / EDIM;
    g_loop[i] /= fmaxf(g_cnt[n], 1.0f);
}

__global__ void scan_off() {   // 1 block, 1024 threads
    __shared__ int part[1024];
    int tid = threadIdx.x;
    const int chunk = (NN + 1023) / 1024;
    int beg = tid * chunk;
    int end = beg + chunk; if (end > NN) end = NN;
    if (beg > NN) beg = NN;
    int s = 0;
    for (int i = beg; i < end; i++) s += g_deg[i];
    part[tid] = s;
    __syncthreads();
    for (int off = 1; off < 1024; off <<= 1) {
        int v = (tid >= off) ? part[tid - off] : 0;
        __syncthreads();
        part[tid] += v;
        __syncthreads();
    }
    int run = tid ? part[tid - 1] : 0;
    for (int i = beg; i < end; i++) {
        g_off[i] = run; g_cur[i] = run;
        run += g_deg[i];
    }
    if (tid == 1023) g_off[NN] = run;
}

__global__ void scatter_csr(const int* __restrict__ dst) {
    int e = blockIdx.x * blockDim.x + threadIdx.x;
    if (e >= EE) return;
    int pos = atomicAdd(&g_cur[dst[e]], 1);
    g_eid[pos] = e;
}

__global__ void pad_x(const float* __restrict__ x) {
    size_t i = blockIdx.x * (size_t)blockDim.x + threadIdx.x;
    if (i >= (size_t)NN * KPAD) return;
    int n = (int)(i / KPAD), c = (int)(i % KPAD);
    g_xp[i] = (c < FIN) ? x[(size_t)n * FIN + c] : 0.0f;
}

// ---------------- SGEMM (BM=BN=128, BK=16, double-buffered) ----------------
__global__ __launch_bounds__(256, 2)
void sgemm(const float* __restrict__ A, const float* __restrict__ B,
           const float* __restrict__ bias, float* __restrict__ C,
           int M, int K, int KB, int Nn, int doRelu) {
    __shared__ float As[2][16][132];
    __shared__ float Bs[2][16][128];
    const int tid = threadIdx.x;
    const int trow = tid >> 4, tcol = tid & 15;
    const int rowBase = blockIdx.y * 128, colBase = blockIdx.x * 128;
    const int ar = tid >> 2;
    const int ac = (tid & 3) << 2;
    const int br = tid >> 5;
    const int bc = (tid & 31) << 2;

    float acc[8][8];
#pragma unroll
    for (int i = 0; i < 8; i++)
#pragma unroll
        for (int j = 0; j < 8; j++) acc[i][j] = 0.0f;

    const int nk = K / 16;

    // initial load
    {
#pragma unroll
        for (int p = 0; p < 2; p++) {
            int row = rowBase + ar + p * 64;
            float4 v = make_float4(0.f, 0.f, 0.f, 0.f);
            if (row < M) v = *(const float4*)(A + (size_t)row * K + ac);
            As[0][ac + 0][ar + p * 64] = v.x;
            As[0][ac + 1][ar + p * 64] = v.y;
            As[0][ac + 2][ar + p * 64] = v.z;
            As[0][ac + 3][ar + p * 64] = v.w;
        }
#pragma unroll
        for (int p = 0; p < 2; p++) {
            int kr = br + p * 8;
            float4 v = make_float4(0.f, 0.f, 0.f, 0.f);
            if (kr < KB) v = *(const float4*)(B + (size_t)kr * Nn + colBase + bc);
            *(float4*)&Bs[0][br + p * 8][bc] = v;
        }
    }
    __syncthreads();

    for (int t = 0; t < nk; t++) {
        int buf = t & 1;
        if (t + 1 < nk) {
            int k0 = (t + 1) * 16;
#pragma unroll
            for (int p = 0; p < 2; p++) {
                int row = rowBase + ar + p * 64;
                float4 v = make_float4(0.f, 0.f, 0.f, 0.f);
                if (row < M) v = *(const float4*)(A + (size_t)row * K + k0 + ac);
                As[buf ^ 1][ac + 0][ar + p * 64] = v.x;
                As[buf ^ 1][ac + 1][ar + p * 64] = v.y;
                As[buf ^ 1][ac + 2][ar + p * 64] = v.z;
                As[buf ^ 1][ac + 3][ar + p * 64] = v.w;
            }
#pragma unroll
            for (int p = 0; p < 2; p++) {
                int kr = k0 + br + p * 8;
                float4 v = make_float4(0.f, 0.f, 0.f, 0.f);
                if (kr < KB) v = *(const float4*)(B + (size_t)kr * Nn + colBase + bc);
                *(float4*)&Bs[buf ^ 1][br + p * 8][bc] = v;
            }
        }
#pragma unroll
        for (int kk = 0; kk < 16; kk++) {
            float a[8], b[8];
            *(float4*)&a[0] = *(const float4*)&As[buf][kk][trow * 8];
            *(float4*)&a[4] = *(const float4*)&As[buf][kk][trow * 8 + 4];
            *(float4*)&b[0] = *(const float4*)&Bs[buf][kk][tcol * 8];
            *(float4*)&b[4] = *(const float4*)&Bs[buf][kk][tcol * 8 + 4];
#pragma unroll
            for (int i = 0; i < 8; i++)
#pragma unroll
                for (int j = 0; j < 8; j++) acc[i][j] += a[i] * b[j];
        }
        __syncthreads();
    }

#pragma unroll
    for (int i = 0; i < 8; i++) {
        int gr = rowBase + trow * 8 + i;
        if (gr >= M) continue;
        float* cp = C + (size_t)gr * Nn + colBase + tcol * 8;
#pragma unroll
        for (int j = 0; j < 8; j++) {
            float v = acc[i][j];
            if (bias) v += bias[colBase + tcol * 8 + j];
            if (doRelu) v = fmaxf(v, 0.0f);
            cp[j] = v;
        }
    }
}

// ---------------- attention ----------------
__global__ void compute_we(const float* __restrict__ line, const float* __restrict__ atte) {
    int idx = threadIdx.x;
    int h = idx / EDIM, c = idx % EDIM;
    float s = 0.0f;
    for (int d = 0; d < DD; d++)
        s += line[(size_t)c * (HH * DD) + h * DD + d] * atte[h * DD + d];
    g_we[idx] = s;
}

__global__ void att_nd(const float* __restrict__ atts, const float* __restrict__ attd) {
    int n = blockIdx.x;
    int h = threadIdx.x >> 5;
    int l = threadIdx.x & 31;
    const float* row = g_hH + (size_t)n * (HH * DD) + h * DD;
    float s = 0.0f, d2 = 0.0f;
#pragma unroll
    for (int i = l; i < DD; i += 32) {
        float v = row[i];
        s += v * atts[h * DD + i];
        d2 += v * attd[h * DD + i];
    }
#pragma unroll
    for (int o = 16; o; o >>= 1) {
        s += __shfl_xor_sync(0xffffffffu, s, o);
        d2 += __shfl_xor_sync(0xffffffffu, d2, o);
    }
    if (l == 0) { g_as[n * HH + h] = s; g_ad[n * HH + h] = d2; }
}

// raw alpha per (entry, head); entries [0,EE)=edges, [EE,ETOT)=self loops
__global__ void alpha_raw(const int* __restrict__ src, const int* __restrict__ dst) {
    int eg = (blockIdx.x * blockDim.x + threadIdx.x) >> 5;
    int l = threadIdx.x & 31;
    if (eg >= ETOT) return;
    int sN, dN;
    const float* row;
    if (eg < EE) {
        sN = src[eg]; dN = dst[eg];
        row = g_ea + (size_t)eg * EDIM;
    } else {
        sN = dN = eg - EE;
        row = g_loop + (size_t)(eg - EE) * EDIM;
    }
    float v = row[l];
    float keep = 0.0f;
#pragma unroll
    for (int h = 0; h < HH; h++) {
        float p = v * g_we[h * EDIM + l];
#pragma unroll
        for (int o = 16; o; o >>= 1) p += __shfl_xor_sync(0xffffffffu, p, o);
        if (l == h) keep = p;
    }
    if (l < HH) {
        float raw = g_as[sN * HH + l] + g_ad[dN * HH + l] + keep;
        raw = raw > 0.0f ? raw : 0.2f * raw;
        g_alpha[(size_t)eg * HH + l] = raw;
    }
}

__device__ __forceinline__ float4 f4max(float4 a, float4 b) {
    return make_float4(fmaxf(a.x, b.x), fmaxf(a.y, b.y), fmaxf(a.z, b.z), fmaxf(a.w, b.w));
}

// fused: per-node softmax + aggregate + head-mean + bias + relu
__global__ void gat_node(const int* __restrict__ src, const float* __restrict__ bias,
                         float* __restrict__ out) {
    int n = blockIdx.x;
    int tid = threadIdx.x;      // 128
    __shared__ float s_mx[4], s_inv[4];
    __shared__ float sbuf[512];
    int p0 = g_off[n], p1 = g_off[n + 1];

    if (tid < 32) {
        int lane = tid;
        float4 selfraw = *(const float4*)(g_alpha + (size_t)(EE + n) * 4);
        float4 mx = selfraw;
        for (int p = p0 + lane; p < p1; p += 32) {
            int eid = g_eid[p];
            float4 r = *(const float4*)(g_alpha + (size_t)eid * 4);
            mx = f4max(mx, r);
        }
#pragma unroll
        for (int o = 16; o; o >>= 1) {
            mx.x = fmaxf(mx.x, __shfl_xor_sync(0xffffffffu, mx.x, o));
            mx.y = fmaxf(mx.y, __shfl_xor_sync(0xffffffffu, mx.y, o));
            mx.z = fmaxf(mx.z, __shfl_xor_sync(0xffffffffu, mx.z, o));
            mx.w = fmaxf(mx.w, __shfl_xor_sync(0xffffffffu, mx.w, o));
        }
        float4 sm = make_float4(0.f, 0.f, 0.f, 0.f);
        if (lane == 0) {
            sm.x = __expf(selfraw.x - mx.x);
            sm.y = __expf(selfraw.y - mx.y);
            sm.z = __expf(selfraw.z - mx.z);
            sm.w = __expf(selfraw.w - mx.w);
        }
        for (int p = p0 + lane; p < p1; p += 32) {
            int eid = g_eid[p];
            float4 r = *(const float4*)(g_alpha + (size_t)eid * 4);
            sm.x += __expf(r.x - mx.x);
            sm.y += __expf(r.y - mx.y);
            sm.z += __expf(r.z - mx.z);
            sm.w += __expf(r.w - mx.w);
        }
#pragma unroll
        for (int o = 16; o; o >>= 1) {
            sm.x += __shfl_xor_sync(0xffffffffu, sm.x, o);
            sm.y += __shfl_xor_sync(0xffffffffu, sm.y, o);
            sm.z += __shfl_xor_sync(0xffffffffu, sm.z, o);
            sm.w += __shfl_xor_sync(0xffffffffu, sm.w, o);
        }
        if (lane == 0) {
            s_mx[0] = mx.x; s_mx[1] = mx.y; s_mx[2] = mx.z; s_mx[3] = mx.w;
            s_inv[0] = 1.0f / (sm.x + 1e-16f);
            s_inv[1] = 1.0f / (sm.y + 1e-16f);
            s_inv[2] = 1.0f / (sm.z + 1e-16f);
            s_inv[3] = 1.0f / (sm.w + 1e-16f);
        }
    }
    __syncthreads();
    int head = tid >> 5;
    float mxh = s_mx[head], invh = s_inv[head];
    const float4* hH4 = (const float4*)g_hH;
    float4 acc = make_float4(0.f, 0.f, 0.f, 0.f);
    for (int p = p0; p < p1; p++) {
        int eid = g_eid[p];
        int s = src[eid];
        float w = __expf(g_alpha[(size_t)eid * 4 + head] - mxh) * invh;
        float4 v = hH4[(size_t)s * 128 + tid];
        acc.x += w * v.x; acc.y += w * v.y; acc.z += w * v.z; acc.w += w * v.w;
    }
    {
        float w = __expf(g_alpha[(size_t)(EE + n) * 4 + head] - mxh) * invh;
        float4 v = hH4[(size_t)n * 128 + tid];
        acc.x += w * v.x; acc.y += w * v.y; acc.z += w * v.z; acc.w += w * v.w;
    }
    *(float4*)&sbuf[tid * 4] = acc;
    __syncthreads();
    if (tid < 32) {
#pragma unroll
        for (int j = 0; j < 4; j++) {
            int d = tid * 4 + j;
            float v = 0.25f * (sbuf[d] + sbuf[128 + d] + sbuf[256 + d] + sbuf[384 + d]) + bias[d];
            out[(size_t)n * 128 + d] = fmaxf(v, 0.0f);
        }
    }
}

// ---------------- host ----------------
static float* symaddr(const void* s) {
    void* p = nullptr;
    cudaGetSymbolAddress(&p, s);
    return (float*)p;
}

extern "C" void kernel_launch(void* const* d_in, const int* in_sizes, int n_in,
                              void* d_out, int out_size) {
    const float* x   = (const float*)d_in[0];
    const int*   ei  = (const int*)d_in[1];
    const int*   et  = (const int*)d_in[2];
    const float* w1  = (const float*)d_in[3];
    const float* b1  = (const float*)d_in[4];
    const float* w2  = (const float*)d_in[5];
    const float* b2  = (const float*)d_in[6];
    const float* rel = (const float*)d_in[7];
    const float* lin[2]  = {(const float*)d_in[8],  (const float*)d_in[14]};
    const float* line[2] = {(const float*)d_in[9],  (const float*)d_in[15]};
    const float* atts[2] = {(const float*)d_in[10], (const float*)d_in[16]};
    const float* attd[2] = {(const float*)d_in[11], (const float*)d_in[17]};
    const float* atte[2] = {(const float*)d_in[12], (const float*)d_in[18]};
    const float* bias[2] = {(const float*)d_in[13], (const float*)d_in[19]};
    const int* srcp = ei;
    const int* dstp = ei + EE;

    float* pxp = symaddr(g_xp);
    float* ph1 = symaddr(g_h1);
    float* px  = symaddr(g_x);
    float* phH = symaddr(g_hH);

    zero_once<<<(NN * EDIM + 255) / 256, 256>>>();
    gather_ea<<<(EE * 32 + 255) / 256, 256>>>(et, dstp, rel);
    loop_div<<<(NN * EDIM + 255) / 256, 256>>>();
    scan_off<<<1, 1024>>>();
    scatter_csr<<<(EE + 255) / 256, 256>>>(dstp);
    pad_x<<<(int)(((size_t)NN * KPAD + 255) / 256), 256>>>(x);

    // node encoder
    sgemm<<<dim3(HID / 128, (NN + 127) / 128), 256>>>(pxp, w1, b1, ph1, NN, KPAD, FIN, HID, 1);
    sgemm<<<dim3(DD / 128, (NN + 127) / 128), 256>>>(ph1, w2, b2, px, NN, HID, HID, DD, 0);

    for (int L = 0; L < 2; L++) {
        compute_we<<<1, HH * EDIM>>>(line[L], atte[L]);
        sgemm<<<dim3((HH * DD) / 128, (NN + 127) / 128), 256>>>(
            px, lin[L], nullptr, phH, NN, DD, DD, HH * DD, 0);
        att_nd<<<NN, 128>>>(atts[L], attd[L]);
        alpha_raw<<<((size_t)ETOT * 32 + 255) / 256, 256>>>(srcp, dstp);
        gat_node<<<NN, 128>>>(srcp, bias[L], (L == 0) ? px : (float*)d_out);
    }
}

// round 3
// speedup vs baseline: 2.3095x; 1.2612x over previous
#include <cuda_runtime.h>
#include <math.h>
#include <stdint.h>

#define NN   20000
#define EE   320000
#define FIN  518
#define KPAD 528
#define DD   128
#define EDIM 32
#define HH   4
#define HID  256
#define ETOT (EE + NN)
#define SCANB ((NN + 127) / 128)

// ---------------- scratch ----------------
__device__ float g_xp[(size_t)NN * KPAD];
__device__ float g_h1[(size_t)NN * HID];
__device__ float g_x[(size_t)NN * DD];
__device__ float g_ea[(size_t)EE * EDIM];
__device__ float g_loop[(size_t)NN * EDIM];
__device__ float g_cnt[NN];
__device__ float g_hH[(size_t)NN * HH * DD];
__device__ float g_as[NN * HH];
__device__ float g_ad[NN * HH];
__device__ float g_alpha[(size_t)ETOT * HH];
__device__ float g_we[HH * EDIM];
__device__ int   g_deg[NN + 1];
__device__ int   g_off[NN + 1];
__device__ int   g_cur[NN];
__device__ int   g_eid[EE];
__device__ int   g_bsum[SCANB];

// ---------------- setup kernels ----------------
__global__ void zero_once() {
    int i = blockIdx.x * blockDim.x + threadIdx.x;
    if (i < NN) g_cnt[i] = 0.0f;
    if (i <= NN) g_deg[i] = 0;
    if (i < NN * EDIM) g_loop[i] = 0.0f;
}

__global__ void gather_ea(const int* __restrict__ et, const int* __restrict__ dst,
                          const float* __restrict__ rel) {
    int eg = (blockIdx.x * blockDim.x + threadIdx.x) >> 5;
    int l = threadIdx.x & 31;
    if (eg >= EE) return;
    int t = et[eg];
    int d = dst[eg];
    float v = rel[t * EDIM + l];
    g_ea[(size_t)eg * EDIM + l] = v;
    atomicAdd(&g_loop[d * EDIM + l], v);
    if (l == 0) {
        atomicAdd(&g_cnt[d], 1.0f);
        atomicAdd(&g_deg[d], 1);
    }
}

__global__ void loop_div() {
    int i = blockIdx.x * blockDim.x + threadIdx.x;
    if (i >= NN * EDIM) return;
    int n = i / EDIM;
    g_loop[i] /= fmaxf(g_cnt[n], 1.0f);
}

// hierarchical exclusive scan of g_deg -> g_off / g_cur
__global__ void scan_k1() {
    int i = blockIdx.x * 128 + threadIdx.x;
    int v = (i < NN) ? g_deg[i] : 0;
#pragma unroll
    for (int o = 16; o; o >>= 1) v += __shfl_xor_sync(0xffffffffu, v, o);
    __shared__ int sm[4];
    if ((threadIdx.x & 31) == 0) sm[threadIdx.x >> 5] = v;
    __syncthreads();
    if (threadIdx.x == 0) g_bsum[blockIdx.x] = sm[0] + sm[1] + sm[2] + sm[3];
}

__global__ void scan_k2() {   // 1 block, 256 threads
    __shared__ int s[256];
    int tid = threadIdx.x;
    int v = (tid < SCANB) ? g_bsum[tid] : 0;
    s[tid] = v;
    __syncthreads();
    for (int o = 1; o < 256; o <<= 1) {
        int t = (tid >= o) ? s[tid - o] : 0;
        __syncthreads();
        s[tid] += t;
        __syncthreads();
    }
    if (tid < SCANB) g_bsum[tid] = s[tid] - v;   // exclusive
}

__global__ void scan_k3() {
    int tid = threadIdx.x;
    int i = blockIdx.x * 128 + tid;
    int lane = tid & 31, warp = tid >> 5;
    int v = (i < NN) ? g_deg[i] : 0;
    int incl = v;
#pragma unroll
    for (int o = 1; o < 32; o <<= 1) {
        int n = __shfl_up_sync(0xffffffffu, incl, o);
        if (lane >= o) incl += n;
    }
    __shared__ int ws[4];
    if (lane == 31) ws[warp] = incl;
    __syncthreads();
    int wbase = 0;
    for (int w = 0; w < warp; w++) wbase += ws[w];
    int excl = g_bsum[blockIdx.x] + wbase + incl - v;
    if (i < NN) {
        g_off[i] = excl;
        g_cur[i] = excl;
        if (i == NN - 1) g_off[NN] = excl + v;
    }
}

__global__ void scatter_csr(const int* __restrict__ dst) {
    int e = blockIdx.x * blockDim.x + threadIdx.x;
    if (e >= EE) return;
    int pos = atomicAdd(&g_cur[dst[e]], 1);
    g_eid[pos] = e;
}

__global__ void pad_x(const float* __restrict__ x) {
    size_t i = blockIdx.x * (size_t)blockDim.x + threadIdx.x;
    if (i >= (size_t)NN * KPAD) return;
    int n = (int)(i / KPAD), c = (int)(i % KPAD);
    g_xp[i] = (c < FIN) ? x[(size_t)n * FIN + c] : 0.0f;
}

// ---------------- tf32 tensor-core GEMM (3xTF32 for fp32 precision) ----------------
__device__ __forceinline__ void tf32_split(float v, uint32_t& hi, uint32_t& lo) {
    uint32_t h;
    asm("cvt.rna.tf32.f32 %0, %1;" : "=r"(h) : "f"(v));
    hi = h;
    lo = __float_as_uint(v - __uint_as_float(h));
}

__device__ __forceinline__ void mma8(float* c, const uint32_t* a, uint32_t b0, uint32_t b1) {
    asm volatile(
        "mma.sync.aligned.m16n8k8.row.col.f32.tf32.tf32.f32 "
        "{%0,%1,%2,%3}, {%4,%5,%6,%7}, {%8,%9}, {%0,%1,%2,%3};\n"
        : "+f"(c[0]), "+f"(c[1]), "+f"(c[2]), "+f"(c[3])
        : "r"(a[0]), "r"(a[1]), "r"(a[2]), "r"(a[3]), "r"(b0), "r"(b1));
}

// C[M,Nn] = A[M,K] @ B[K,Nn]; B has KB valid rows (K padded); optional bias/relu.
__global__ __launch_bounds__(256, 2)
void mma_gemm(const float* __restrict__ A, const float* __restrict__ B,
              const float* __restrict__ bias, float* __restrict__ C,
              int M, int K, int KB, int Nn, int doRelu) {
    __shared__ float As[2][16][136];
    __shared__ float Bs[2][16][136];
    const int tid = threadIdx.x;
    const int warp = tid >> 5, lane = tid & 31;
    const int g = lane >> 2, tg = lane & 3;
    const int warpM = warp >> 1, warpN = warp & 1;     // 4 x 2 warps, tile 32x64
    const int rowBase = blockIdx.y * 128, colBase = blockIdx.x * 128;

    const int arow = tid >> 1, acol = (tid & 1) * 8;
    const int brow = tid >> 4, bcol = (tid & 15) * 8;

    float acc[2][8][4];
#pragma unroll
    for (int mi = 0; mi < 2; mi++)
#pragma unroll
        for (int ni = 0; ni < 8; ni++)
#pragma unroll
            for (int r = 0; r < 4; r++) acc[mi][ni][r] = 0.0f;

    const int nk = K / 16;

#define LOAD_TILES(BUF, K0)                                                       \
    {                                                                             \
        int grow = rowBase + arow;                                                \
        _Pragma("unroll")                                                         \
        for (int h = 0; h < 2; h++) {                                             \
            float4 v = make_float4(0.f, 0.f, 0.f, 0.f);                           \
            if (grow < M) v = *(const float4*)(A + (size_t)grow * K + (K0) + acol + h * 4); \
            As[BUF][acol + h * 4 + 0][arow] = v.x;                                \
            As[BUF][acol + h * 4 + 1][arow] = v.y;                                \
            As[BUF][acol + h * 4 + 2][arow] = v.z;                                \
            As[BUF][acol + h * 4 + 3][arow] = v.w;                                \
        }                                                                         \
        int kr = (K0) + brow;                                                     \
        _Pragma("unroll")                                                         \
        for (int h = 0; h < 2; h++) {                                             \
            float4 v = make_float4(0.f, 0.f, 0.f, 0.f);                           \
            if (kr < KB) v = *(const float4*)(B + (size_t)kr * Nn + colBase + bcol + h * 4); \
            *(float4*)&Bs[BUF][brow][bcol + h * 4] = v;                           \
        }                                                                         \
    }

    LOAD_TILES(0, 0)
    __syncthreads();

    for (int t = 0; t < nk; t++) {
        int buf = t & 1;
        if (t + 1 < nk) LOAD_TILES(buf ^ 1, (t + 1) * 16)

#pragma unroll
        for (int ks = 0; ks < 16; ks += 8) {
            uint32_t ahi[2][4], alo[2][4];
#pragma unroll
            for (int mi = 0; mi < 2; mi++) {
                int mb = warpM * 32 + mi * 16 + g;
                tf32_split(As[buf][ks + tg][mb],         ahi[mi][0], alo[mi][0]);
                tf32_split(As[buf][ks + tg][mb + 8],     ahi[mi][1], alo[mi][1]);
                tf32_split(As[buf][ks + tg + 4][mb],     ahi[mi][2], alo[mi][2]);
                tf32_split(As[buf][ks + tg + 4][mb + 8], ahi[mi][3], alo[mi][3]);
            }
#pragma unroll
            for (int ni = 0; ni < 8; ni++) {
                int nb = warpN * 64 + ni * 8 + g;
                uint32_t bh0, bl0, bh1, bl1;
                tf32_split(Bs[buf][ks + tg][nb],     bh0, bl0);
                tf32_split(Bs[buf][ks + tg + 4][nb], bh1, bl1);
#pragma unroll
                for (int mi = 0; mi < 2; mi++) {
                    mma8(acc[mi][ni], alo[mi], bh0, bh1);
                    mma8(acc[mi][ni], ahi[mi], bl0, bl1);
                    mma8(acc[mi][ni], ahi[mi], bh0, bh1);
                }
            }
        }
        __syncthreads();
    }

#pragma unroll
    for (int mi = 0; mi < 2; mi++) {
        int r0 = rowBase + warpM * 32 + mi * 16 + g;
#pragma unroll
        for (int ni = 0; ni < 8; ni++) {
            int c0 = colBase + warpN * 64 + ni * 8 + tg * 2;
            float bb0 = bias ? bias[c0] : 0.0f;
            float bb1 = bias ? bias[c0 + 1] : 0.0f;
            if (r0 < M) {
                float v0 = acc[mi][ni][0] + bb0;
                float v1 = acc[mi][ni][1] + bb1;
                if (doRelu) { v0 = fmaxf(v0, 0.f); v1 = fmaxf(v1, 0.f); }
                C[(size_t)r0 * Nn + c0] = v0;
                C[(size_t)r0 * Nn + c0 + 1] = v1;
            }
            if (r0 + 8 < M) {
                float v2 = acc[mi][ni][2] + bb0;
                float v3 = acc[mi][ni][3] + bb1;
                if (doRelu) { v2 = fmaxf(v2, 0.f); v3 = fmaxf(v3, 0.f); }
                C[(size_t)(r0 + 8) * Nn + c0] = v2;
                C[(size_t)(r0 + 8) * Nn + c0 + 1] = v3;
            }
        }
    }
#undef LOAD_TILES
}

// ---------------- attention ----------------
__global__ void compute_we(const float* __restrict__ line, const float* __restrict__ atte) {
    int idx = threadIdx.x;
    int h = idx / EDIM, c = idx % EDIM;
    float s = 0.0f;
    for (int d = 0; d < DD; d++)
        s += line[(size_t)c * (HH * DD) + h * DD + d] * atte[h * DD + d];
    g_we[idx] = s;
}

__global__ void att_nd(const float* __restrict__ atts, const float* __restrict__ attd) {
    int n = blockIdx.x;
    int h = threadIdx.x >> 5;
    int l = threadIdx.x & 31;
    const float* row = g_hH + (size_t)n * (HH * DD) + h * DD;
    float s = 0.0f, d2 = 0.0f;
#pragma unroll
    for (int i = l; i < DD; i += 32) {
        float v = row[i];
        s += v * atts[h * DD + i];
        d2 += v * attd[h * DD + i];
    }
#pragma unroll
    for (int o = 16; o; o >>= 1) {
        s += __shfl_xor_sync(0xffffffffu, s, o);
        d2 += __shfl_xor_sync(0xffffffffu, d2, o);
    }
    if (l == 0) { g_as[n * HH + h] = s; g_ad[n * HH + h] = d2; }
}

__global__ void alpha_raw(const int* __restrict__ src, const int* __restrict__ dst) {
    int eg = (blockIdx.x * blockDim.x + threadIdx.x) >> 5;
    int l = threadIdx.x & 31;
    if (eg >= ETOT) return;
    int sN, dN;
    const float* row;
    if (eg < EE) {
        sN = src[eg]; dN = dst[eg];
        row = g_ea + (size_t)eg * EDIM;
    } else {
        sN = dN = eg - EE;
        row = g_loop + (size_t)(eg - EE) * EDIM;
    }
    float v = row[l];
    float keep = 0.0f;
#pragma unroll
    for (int h = 0; h < HH; h++) {
        float p = v * g_we[h * EDIM + l];
#pragma unroll
        for (int o = 16; o; o >>= 1) p += __shfl_xor_sync(0xffffffffu, p, o);
        if (l == h) keep = p;
    }
    if (l < HH) {
        float raw = g_as[sN * HH + l] + g_ad[dN * HH + l] + keep;
        raw = raw > 0.0f ? raw : 0.2f * raw;
        g_alpha[(size_t)eg * HH + l] = raw;
    }
}

__device__ __forceinline__ float4 f4max(float4 a, float4 b) {
    return make_float4(fmaxf(a.x, b.x), fmaxf(a.y, b.y), fmaxf(a.z, b.z), fmaxf(a.w, b.w));
}

__global__ void gat_node(const int* __restrict__ src, const float* __restrict__ bias,
                         float* __restrict__ out) {
    int n = blockIdx.x;
    int tid = threadIdx.x;      // 128
    __shared__ float s_mx[4], s_inv[4];
    __shared__ float sbuf[512];
    int p0 = g_off[n], p1 = g_off[n + 1];

    if (tid < 32) {
        int lane = tid;
        float4 selfraw = *(const float4*)(g_alpha + (size_t)(EE + n) * 4);
        float4 mx = selfraw;
        for (int p = p0 + lane; p < p1; p += 32) {
            int eid = g_eid[p];
            float4 r = *(const float4*)(g_alpha + (size_t)eid * 4);
            mx = f4max(mx, r);
        }
#pragma unroll
        for (int o = 16; o; o >>= 1) {
            mx.x = fmaxf(mx.x, __shfl_xor_sync(0xffffffffu, mx.x, o));
            mx.y = fmaxf(mx.y, __shfl_xor_sync(0xffffffffu, mx.y, o));
            mx.z = fmaxf(mx.z, __shfl_xor_sync(0xffffffffu, mx.z, o));
            mx.w = fmaxf(mx.w, __shfl_xor_sync(0xffffffffu, mx.w, o));
        }
        float4 sm = make_float4(0.f, 0.f, 0.f, 0.f);
        if (lane == 0) {
            sm.x = __expf(selfraw.x - mx.x);
            sm.y = __expf(selfraw.y - mx.y);
            sm.z = __expf(selfraw.z - mx.z);
            sm.w = __expf(selfraw.w - mx.w);
        }
        for (int p = p0 + lane; p < p1; p += 32) {
            int eid = g_eid[p];
            float4 r = *(const float4*)(g_alpha + (size_t)eid * 4);
            sm.x += __expf(r.x - mx.x);
            sm.y += __expf(r.y - mx.y);
            sm.z += __expf(r.z - mx.z);
            sm.w += __expf(r.w - mx.w);
        }
#pragma unroll
        for (int o = 16; o; o >>= 1) {
            sm.x += __shfl_xor_sync(0xffffffffu, sm.x, o);
            sm.y += __shfl_xor_sync(0xffffffffu, sm.y, o);
            sm.z += __shfl_xor_sync(0xffffffffu, sm.z, o);
            sm.w += __shfl_xor_sync(0xffffffffu, sm.w, o);
        }
        if (lane == 0) {
            s_mx[0] = mx.x; s_mx[1] = mx.y; s_mx[2] = mx.z; s_mx[3] = mx.w;
            s_inv[0] = 1.0f / (sm.x + 1e-16f);
            s_inv[1] = 1.0f / (sm.y + 1e-16f);
            s_inv[2] = 1.0f / (sm.z + 1e-16f);
            s_inv[3] = 1.0f / (sm.w + 1e-16f);
        }
    }
    __syncthreads();
    int head = tid >> 5;
    float mxh = s_mx[head], invh = s_inv[head];
    const float4* hH4 = (const float4*)g_hH;
    float4 acc = make_float4(0.f, 0.f, 0.f, 0.f);
    for (int p = p0; p < p1; p++) {
        int eid = g_eid[p];
        int s = src[eid];
        float w = __expf(g_alpha[(size_t)eid * 4 + head] - mxh) * invh;
        float4 v = hH4[(size_t)s * 128 + tid];
        acc.x += w * v.x; acc.y += w * v.y; acc.z += w * v.z; acc.w += w * v.w;
    }
    {
        float w = __expf(g_alpha[(size_t)(EE + n) * 4 + head] - mxh) * invh;
        float4 v = hH4[(size_t)n * 128 + tid];
        acc.x += w * v.x; acc.y += w * v.y; acc.z += w * v.z; acc.w += w * v.w;
    }
    *(float4*)&sbuf[tid * 4] = acc;
    __syncthreads();
    if (tid < 32) {
#pragma unroll
        for (int j = 0; j < 4; j++) {
            int d = tid * 4 + j;
            float v = 0.25f * (sbuf[d] + sbuf[128 + d] + sbuf[256 + d] + sbuf[384 + d]) + bias[d];
            out[(size_t)n * 128 + d] = fmaxf(v, 0.0f);
        }
    }
}

// ---------------- host ----------------
static float* symaddr(const void* s) {
    void* p = nullptr;
    cudaGetSymbolAddress(&p, s);
    return (float*)p;
}

extern "C" void kernel_launch(void* const* d_in, const int* in_sizes, int n_in,
                              void* d_out, int out_size) {
    const float* x   = (const float*)d_in[0];
    const int*   ei  = (const int*)d_in[1];
    const int*   et  = (const int*)d_in[2];
    const float* w1  = (const float*)d_in[3];
    const float* b1  = (const float*)d_in[4];
    const float* w2  = (const float*)d_in[5];
    const float* b2  = (const float*)d_in[6];
    const float* rel = (const float*)d_in[7];
    const float* lin[2]  = {(const float*)d_in[8],  (const float*)d_in[14]};
    const float* line[2] = {(const float*)d_in[9],  (const float*)d_in[15]};
    const float* atts[2] = {(const float*)d_in[10], (const float*)d_in[16]};
    const float* attd[2] = {(const float*)d_in[11], (const float*)d_in[17]};
    const float* atte[2] = {(const float*)d_in[12], (const float*)d_in[18]};
    const float* bias[2] = {(const float*)d_in[13], (const float*)d_in[19]};
    const int* srcp = ei;
    const int* dstp = ei + EE;

    float* pxp = symaddr(g_xp);
    float* ph1 = symaddr(g_h1);
    float* px  = symaddr(g_x);
    float* phH = symaddr(g_hH);

    zero_once<<<(NN * EDIM + 255) / 256, 256>>>();
    gather_ea<<<(EE * 32 + 255) / 256, 256>>>(et, dstp, rel);
    loop_div<<<(NN * EDIM + 255) / 256, 256>>>();
    scan_k1<<<SCANB, 128>>>();
    scan_k2<<<1, 256>>>();
    scan_k3<<<SCANB, 128>>>();
    scatter_csr<<<(EE + 255) / 256, 256>>>(dstp);
    pad_x<<<(int)(((size_t)NN * KPAD + 255) / 256), 256>>>(x);

    // node encoder
    mma_gemm<<<dim3(HID / 128, (NN + 127) / 128), 256>>>(pxp, w1, b1, ph1, NN, KPAD, FIN, HID, 1);
    mma_gemm<<<dim3(DD / 128, (NN + 127) / 128), 256>>>(ph1, w2, b2, px, NN, HID, HID, DD, 0);

    for (int L = 0; L < 2; L++) {
        compute_we<<<1, HH * EDIM>>>(line[L], atte[L]);
        mma_gemm<<<dim3((HH * DD) / 128, (NN + 127) / 128), 256>>>(
            px, lin[L], nullptr, phH, NN, DD, DD, HH * DD, 0);
        att_nd<<<NN, 128>>>(atts[L], attd[L]);
        alpha_raw<<<((size_t)ETOT * 32 + 255) / 256, 256>>>(srcp, dstp);
        gat_node<<<NN, 128>>>(srcp, bias[L], (L == 0) ? px : (float*)d_out);
    }
}